// round 8
// baseline (speedup 1.0000x reference)
#include <cuda_runtime.h>
#include <math.h>

#define NB 8
#define NC 256
#define NH 128
#define NW 128
#define HW (NH*NW)

// ---------------- scratch (device globals; no allocs allowed) ----------------
__device__ __align__(16) float g_kpre[NB][HW];
__device__ __align__(16) float g_ux[NB][HW];
__device__ __align__(16) float g_wsm[NB][HW];
__device__ __align__(16) float g_s[NB][HW];
__device__ float g_hmax[NB][NH];
__device__ float g_hsum[NB][NH];
__device__ float g_wmax[NB][NW];
__device__ float g_wsum[NB][NW];
__device__ float g_m[NB];
__device__ float g_xk[NB][NC];
__device__ float g_cf[NB][NC];
__device__ float g_u[NC];
__device__ float g_beta;

__device__ __forceinline__ void atomicMaxFloat(float* addr, float val) {
    // sign-aware int-punning float atomic max
    if (val >= 0.f) atomicMax((int*)addr, __float_as_int(val));
    else            atomicMin((unsigned int*)addr, __float_as_uint(val));
}

// ---------------- kernel 0: init stats + precompute u = v_w^T w3, beta ------
__global__ __launch_bounds__(256) void k_init(const float* __restrict__ vw,
                                              const float* __restrict__ vb,
                                              const float* __restrict__ w3) {
    int t = threadIdx.x;
    if (blockIdx.x < NB) {
        int b = blockIdx.x;
        if (t < NH) {
            g_hmax[b][t] = -INFINITY; g_hsum[b][t] = 0.f;
            g_wmax[b][t] = -INFINITY; g_wsum[b][t] = 0.f;
        }
        if (t == 0) g_m[b] = -INFINITY;
    } else {
        // u[c] = sum_o w3[o] * vw[o*NC + c]
        float acc = 0.f;
#pragma unroll 8
        for (int o = 0; o < NC; o++) acc = fmaf(w3[o], vw[o*NC + t], acc);
        g_u[t] = acc;
        if (t == 0) {
            float ba = 0.f;
            for (int c = 0; c < NC; c++) ba = fmaf(w3[c], vb[c], ba);
            g_beta = ba;
        }
    }
}

// ---------------- kernel 1: one full read of x ------------------------------
// per position n: k_pre = kw.x + kb, ux = u.x ; per (b,h): max/sum over (c,w);
// per (b,w): max/sum over (c,h); per b: max of k_pre for softmax.
__global__ __launch_bounds__(256) void k_pass1(const float* __restrict__ x,
                                               const float* __restrict__ kw_g,
                                               const float* __restrict__ kb_p) {
    __shared__ float s_kw[NC], s_u[NC];
    __shared__ float s_a[256], s_b[256];
    const int t  = threadIdx.x;
    const int b  = blockIdx.y;
    s_kw[t] = kw_g[t];
    s_u[t]  = g_u[t];
    __syncthreads();

    const int rl = t >> 7;            // 0..1 (row within block)
    const int wl = t & 127;           // 0..127 (w column)
    const int h  = blockIdx.x * 2 + rl;
    const int n  = h * NW + wl;
    const float* xb = x + (size_t)b * NC * HW + n;

    float kp = 0.f, uxv = 0.f, pmax = -INFINITY, psum = 0.f;
#pragma unroll 8
    for (int c = 0; c < NC; c++) {
        float v = xb[(size_t)c * HW];
        kp   = fmaf(s_kw[c], v, kp);
        uxv  = fmaf(s_u[c],  v, uxv);
        pmax = fmaxf(pmax, v);
        psum += v;
    }
    kp += kb_p[0];
    g_kpre[b][n] = kp;
    g_ux[b][n]   = uxv;

    // --- h-row reduction: 128 threads of each row own the full (c,w) set ---
    s_a[t] = pmax; s_b[t] = psum;
    __syncthreads();
    for (int off = 64; off > 0; off >>= 1) {
        if (wl < off) {
            s_a[t] = fmaxf(s_a[t], s_a[t + off]);
            s_b[t] += s_b[t + off];
        }
        __syncthreads();
    }
    if (wl == 0) { g_hmax[b][h] = s_a[t]; g_hsum[b][h] = s_b[t]; }
    __syncthreads();

    // --- w-column partials: pair-combine the 2 rows, then atomics ----------
    s_a[t] = pmax; s_b[t] = psum;
    __syncthreads();
    if (t < 128) {
        float m2 = fmaxf(s_a[t], s_a[t + 128]);
        float su = s_b[t] + s_b[t + 128];
        atomicMaxFloat(&g_wmax[b][t], m2);
        atomicAdd(&g_wsum[b][t], su);
    }
    __syncthreads();

    // --- block max of k_pre -> batch softmax max ---------------------------
    s_a[t] = kp;
    __syncthreads();
    for (int off = 128; off > 0; off >>= 1) {
        if (t < off) s_a[t] = fmaxf(s_a[t], s_a[t + off]);
        __syncthreads();
    }
    if (t == 0) atomicMaxFloat(&g_m[b], s_a[0]);
}

// ---------------- kernel 2: softmax weights, attentions, s map --------------
__global__ __launch_bounds__(256) void k_soft(const float* __restrict__ w1,
                                              const float* __restrict__ b1,
                                              const float* __restrict__ w2,
                                              const float* __restrict__ b2,
                                              const float* __restrict__ b3) {
    const int b = blockIdx.x, t = threadIdx.x;
    __shared__ float s_red[256];
    __shared__ float s_invZ;
    __shared__ float s_hatt[NH], s_watt[NW];

    const float m = g_m[b];
    float zs = 0.f;
#pragma unroll 4
    for (int n = t; n < HW; n += 256) zs += __expf(g_kpre[b][n] - m);
    s_red[t] = zs;
    __syncthreads();
    for (int off = 128; off > 0; off >>= 1) {
        if (t < off) s_red[t] += s_red[t + off];
        __syncthreads();
    }
    if (t == 0) s_invZ = 1.f / s_red[0];
    __syncthreads();
    const float invZ = s_invZ;
#pragma unroll 4
    for (int n = t; n < HW; n += 256)
        g_wsm[b][n] = __expf(g_kpre[b][n] - m) * invZ;

    if (t < NH) {
        float havg = g_hsum[b][t] * (1.f / (NC * NW));
        float v = fmaf(w1[0], g_hmax[b][t], fmaf(w1[1], havg, b1[0]));
        s_hatt[t] = 1.f / (1.f + __expf(-v));
    } else {
        int w = t - 128;
        float wavg = g_wsum[b][w] * (1.f / (NC * NH));
        float v = fmaf(w2[0], g_wmax[b][w], fmaf(w2[1], wavg, b2[0]));
        s_watt[w] = 1.f / (1.f + __expf(-v));
    }
    __syncthreads();

    const float beta = g_beta, bb3 = b3[0];
#pragma unroll 4
    for (int n = t; n < HW; n += 256) {
        int hh = n >> 7, ww = n & 127;
        float att = s_hatt[hh] + s_watt[ww];
        float sp  = fmaf(att, g_ux[b][n] + beta, bb3);
        g_s[b][n] = 1.f / (1.f + __expf(-sp));
    }
}

// ---------------- kernel 3: xk[b,c] = sum_n x[b,c,n] * softmax_w[b,n] -------
__global__ __launch_bounds__(256) void k_xk(const float* __restrict__ x) {
    const int b = blockIdx.y, c = blockIdx.x, t = threadIdx.x;
    const float4* x4 = (const float4*)(x + ((size_t)b * NC + c) * HW);
    const float4* w4 = (const float4*)g_wsm[b];
    float acc = 0.f;
#pragma unroll 16
    for (int i = 0; i < HW / 4 / 256; i++) {   // 16 iters
        int j = t + i * 256;
        float4 xv = x4[j], wv = w4[j];
        acc = fmaf(xv.x, wv.x, acc);
        acc = fmaf(xv.y, wv.y, acc);
        acc = fmaf(xv.z, wv.z, acc);
        acc = fmaf(xv.w, wv.w, acc);
    }
    __shared__ float s_red[256];
    s_red[t] = acc;
    __syncthreads();
    for (int off = 128; off > 0; off >>= 1) {
        if (t < off) s_red[t] += s_red[t + off];
        __syncthreads();
    }
    if (t == 0) g_xk[b][c] = s_red[0];
}

// ---------------- kernel 4: channel_fea = v_w @ xk + v_b --------------------
__global__ __launch_bounds__(256) void k_cf(const float* __restrict__ vw,
                                            const float* __restrict__ vb) {
    const int b = blockIdx.x, o = threadIdx.x;
    __shared__ float s_xk[NC];
    s_xk[o] = g_xk[b][o];
    __syncthreads();
    float acc = vb[o];
#pragma unroll 8
    for (int c = 0; c < NC; c++) acc = fmaf(vw[o * NC + c], s_xk[c], acc);
    g_cf[b][o] = acc;
}

// ---------------- kernel 5: out = s[b,n]*cf[b,c] + x ------------------------
__global__ __launch_bounds__(256) void k_out(const float* __restrict__ x,
                                             float* __restrict__ out) {
    const size_t i4 = (size_t)blockIdx.x * 256 + threadIdx.x;  // float4 index
    const size_t i  = i4 * 4;
    const int n  = (int)(i & (HW - 1));
    const int bc = (int)(i >> 14);
    const int b  = bc >> 8;
    const int c  = bc & 255;
    float4 xv = ((const float4*)x)[i4];
    float4 sv = *(const float4*)&g_s[b][n];
    float  cf = g_cf[b][c];
    float4 o;
    o.x = fmaf(sv.x, cf, xv.x);
    o.y = fmaf(sv.y, cf, xv.y);
    o.z = fmaf(sv.z, cf, xv.z);
    o.w = fmaf(sv.w, cf, xv.w);
    ((float4*)out)[i4] = o;
}

// ---------------- launch ----------------------------------------------------
extern "C" void kernel_launch(void* const* d_in, const int* in_sizes, int n_in,
                              void* d_out, int out_size) {
    const float* x  = (const float*)d_in[0];
    const float* vw = (const float*)d_in[1];
    const float* vb = (const float*)d_in[2];
    const float* kw = (const float*)d_in[3];
    const float* kb = (const float*)d_in[4];
    const float* w1 = (const float*)d_in[5];
    const float* b1 = (const float*)d_in[6];
    const float* w2 = (const float*)d_in[7];
    const float* b2 = (const float*)d_in[8];
    const float* w3 = (const float*)d_in[9];
    const float* b3 = (const float*)d_in[10];
    float* out = (float*)d_out;

    k_init<<<NB + 1, 256>>>(vw, vb, w3);
    dim3 g1(NH / 2, NB);
    k_pass1<<<g1, 256>>>(x, kw, kb);
    k_soft<<<NB, 256>>>(w1, b1, w2, b2, b3);
    dim3 g3(NC, NB);
    k_xk<<<g3, 256>>>(x);
    k_cf<<<NB, 256>>>(vw, vb);
    k_out<<<(NB * NC * HW / 4) / 256, 256>>>(x, out);
}

// round 14
// speedup vs baseline: 1.3104x; 1.3104x over previous
#include <cuda_runtime.h>
#include <math.h>

#define NB 8
#define NC 256
#define NH 128
#define NW 128
#define HW (NH*NW)

// ---------------- scratch (device globals) ----------------------------------
__device__ __align__(16) float g_ux[NB][HW];
__device__ __align__(16) float g_wsm[NB][HW];   // UNNORMALIZED exp(k_pre)
__device__ __align__(16) float g_s[NB][HW];
__device__ float g_hmax[NB][NH];
__device__ float g_hsum[NB][NH];
__device__ float g_wmax[NB][NW];
__device__ float g_wsum[NB][NW];
__device__ float g_Z[NB];                        // softmax partition sum
__device__ float g_xk[NB][NC];                   // unnormalized weighted sum
__device__ float g_cf[NB][NC];
__device__ float g_u[NC];
__device__ float g_beta;

__device__ __forceinline__ void atomicMaxFloat(float* addr, float val) {
    if (val >= 0.f) atomicMax((int*)addr, __float_as_int(val));
    else            atomicMin((unsigned int*)addr, __float_as_uint(val));
}

// ---------------- kernel 0: init stats + u = v_w^T w3, beta -----------------
__global__ __launch_bounds__(256) void k_init(const float* __restrict__ vw,
                                              const float* __restrict__ vb,
                                              const float* __restrict__ w3) {
    int t = threadIdx.x;
    if (blockIdx.x < NB) {
        int b = blockIdx.x;
        if (t < NH) {
            g_hmax[b][t] = -INFINITY; g_hsum[b][t] = 0.f;
            g_wmax[b][t] = -INFINITY; g_wsum[b][t] = 0.f;
        }
        if (t == 0) g_Z[b] = 0.f;
    } else {
        // coalesced: inner loop over o, consecutive t read consecutive addrs
        float acc = 0.f;
#pragma unroll 8
        for (int o = 0; o < NC; o++) acc = fmaf(w3[o], vw[o*NC + t], acc);
        g_u[t] = acc;
        if (t == 0) {
            float ba = 0.f;
            for (int c = 0; c < NC; c++) ba = fmaf(w3[c], vb[c], ba);
            g_beta = ba;
        }
    }
}

// ---------------- kernel 1: one full read of x ------------------------------
__global__ __launch_bounds__(256) void k_pass1(const float* __restrict__ x,
                                               const float* __restrict__ kw_g,
                                               const float* __restrict__ kb_p) {
    __shared__ float s_kw[NC], s_u[NC];
    __shared__ float s_a[256], s_b[256];
    const int t  = threadIdx.x;
    const int b  = blockIdx.y;
    s_kw[t] = kw_g[t];
    s_u[t]  = g_u[t];
    __syncthreads();

    const int rl = t >> 7;
    const int wl = t & 127;
    const int h  = blockIdx.x * 2 + rl;
    const int n  = h * NW + wl;
    const float* xb = x + (size_t)b * NC * HW + n;

    float kp = 0.f, uxv = 0.f, pmax = -INFINITY, psum = 0.f;
#pragma unroll 16
    for (int c = 0; c < NC; c++) {
        float v = xb[(size_t)c * HW];
        kp   = fmaf(s_kw[c], v, kp);
        uxv  = fmaf(s_u[c],  v, uxv);
        pmax = fmaxf(pmax, v);
        psum += v;
    }
    kp += kb_p[0];
    const float e = __expf(kp);          // unnormalized softmax weight
    g_wsm[b][n] = e;
    g_ux[b][n]  = uxv;

    // --- h-row reduction ----------------------------------------------------
    s_a[t] = pmax; s_b[t] = psum;
    __syncthreads();
    for (int off = 64; off > 0; off >>= 1) {
        if (wl < off) {
            s_a[t] = fmaxf(s_a[t], s_a[t + off]);
            s_b[t] += s_b[t + off];
        }
        __syncthreads();
    }
    if (wl == 0) { g_hmax[b][h] = s_a[t]; g_hsum[b][h] = s_b[t]; }
    __syncthreads();

    // --- w-column partials --------------------------------------------------
    s_a[t] = pmax; s_b[t] = psum;
    __syncthreads();
    if (t < 128) {
        float m2 = fmaxf(s_a[t], s_a[t + 128]);
        float su = s_b[t] + s_b[t + 128];
        atomicMaxFloat(&g_wmax[b][t], m2);
        atomicAdd(&g_wsum[b][t], su);
    }
    __syncthreads();

    // --- block partial of Z = sum exp(kp) -----------------------------------
    s_a[t] = e;
    __syncthreads();
    for (int off = 128; off > 0; off >>= 1) {
        if (t < off) s_a[t] += s_a[t + off];
        __syncthreads();
    }
    if (t == 0) atomicAdd(&g_Z[b], s_a[0]);
}

// ---------------- kernel 2: attentions (smem) + s map, wide grid ------------
__global__ __launch_bounds__(256) void k_smap(const float* __restrict__ w1,
                                              const float* __restrict__ b1,
                                              const float* __restrict__ w2,
                                              const float* __restrict__ b2,
                                              const float* __restrict__ b3) {
    __shared__ float s_att[256];         // [0:128) hatt, [128:256) watt
    const int b = blockIdx.y, t = threadIdx.x;

    if (t < NH) {
        float havg = g_hsum[b][t] * (1.f / (NC * NW));
        float v = fmaf(w1[0], g_hmax[b][t], fmaf(w1[1], havg, b1[0]));
        s_att[t] = 1.f / (1.f + __expf(-v));
    } else {
        int w = t - 128;
        float wavg = g_wsum[b][w] * (1.f / (NC * NH));
        float v = fmaf(w2[0], g_wmax[b][w], fmaf(w2[1], wavg, b2[0]));
        s_att[t] = 1.f / (1.f + __expf(-v));
    }
    __syncthreads();

    const float beta = g_beta, bb3 = b3[0];
    const int base = blockIdx.x * 1024;
#pragma unroll
    for (int i = 0; i < 4; i++) {
        int n  = base + t + i * 256;
        int hh = n >> 7, ww = n & 127;
        float att = s_att[hh] + s_att[128 + ww];
        float sp  = fmaf(att, g_ux[b][n] + beta, bb3);
        g_s[b][n] = 1.f / (1.f + __expf(-sp));
    }
}

// ---------------- kernel 3: xk[b,c] = sum_n x * e[n]  (unnormalized) --------
__global__ __launch_bounds__(256) void k_xk(const float* __restrict__ x) {
    const int b = blockIdx.y, c = blockIdx.x, t = threadIdx.x;
    const float4* x4 = (const float4*)(x + ((size_t)b * NC + c) * HW);
    const float4* w4 = (const float4*)g_wsm[b];
    float acc = 0.f;
#pragma unroll 16
    for (int i = 0; i < HW / 4 / 256; i++) {
        int j = t + i * 256;
        float4 xv = x4[j], wv = w4[j];
        acc = fmaf(xv.x, wv.x, acc);
        acc = fmaf(xv.y, wv.y, acc);
        acc = fmaf(xv.z, wv.z, acc);
        acc = fmaf(xv.w, wv.w, acc);
    }
    __shared__ float s_red[256];
    s_red[t] = acc;
    __syncthreads();
    for (int off = 128; off > 0; off >>= 1) {
        if (t < off) s_red[t] += s_red[t + off];
        __syncthreads();
    }
    if (t == 0) g_xk[b][c] = s_red[0];
}

// ---------------- kernel 4: cf = (v_w @ xk)/Z + v_b  (coalesced) ------------
// warp-per-output: lanes read the vw row as float4, shfl-reduce.
__global__ __launch_bounds__(256) void k_cf(const float* __restrict__ vw,
                                            const float* __restrict__ vb) {
    const int b    = blockIdx.y;
    const int warp = threadIdx.x >> 5;
    const int lane = threadIdx.x & 31;
    const int o    = blockIdx.x * 8 + warp;
    __shared__ float s_xk[NC];
    s_xk[threadIdx.x] = g_xk[b][threadIdx.x];
    __syncthreads();

    const float4* vw4 = (const float4*)(vw + (size_t)o * NC);
    float acc = 0.f;
#pragma unroll
    for (int half = 0; half < 2; half++) {
        float4 v = vw4[half * 32 + lane];      // coalesced 128B per warp
        int cb = (half * 32 + lane) * 4;
        acc = fmaf(v.x, s_xk[cb + 0], acc);
        acc = fmaf(v.y, s_xk[cb + 1], acc);
        acc = fmaf(v.z, s_xk[cb + 2], acc);
        acc = fmaf(v.w, s_xk[cb + 3], acc);
    }
#pragma unroll
    for (int off = 16; off > 0; off >>= 1)
        acc += __shfl_down_sync(0xffffffffu, acc, off);
    if (lane == 0)
        g_cf[b][o] = fmaf(acc, 1.f / g_Z[b], vb[o]);
}

// ---------------- kernel 5: out = s*cf + x, 4 channels per block ------------
__global__ __launch_bounds__(256) void k_out(const float* __restrict__ x,
                                             float* __restrict__ out) {
    const int b  = blockIdx.z;
    const int cg = blockIdx.y;               // channel group of 4
    const int n4 = blockIdx.x * 256 + threadIdx.x;   // float4 idx in [0,4096)

    const float4 sv = ((const float4*)g_s[b])[n4];
    float cf[4];
#pragma unroll
    for (int i = 0; i < 4; i++) cf[i] = g_cf[b][cg * 4 + i];

    const size_t base = ((size_t)(b * NC + cg * 4)) * (HW / 4) + n4;
    const float4* x4 = (const float4*)x;
    float4*       o4 = (float4*)out;
#pragma unroll
    for (int i = 0; i < 4; i++) {
        float4 xv = x4[base + (size_t)i * (HW / 4)];
        float4 o;
        o.x = fmaf(sv.x, cf[i], xv.x);
        o.y = fmaf(sv.y, cf[i], xv.y);
        o.z = fmaf(sv.z, cf[i], xv.z);
        o.w = fmaf(sv.w, cf[i], xv.w);
        o4[base + (size_t)i * (HW / 4)] = o;
    }
}

// ---------------- launch ----------------------------------------------------
extern "C" void kernel_launch(void* const* d_in, const int* in_sizes, int n_in,
                              void* d_out, int out_size) {
    const float* x  = (const float*)d_in[0];
    const float* vw = (const float*)d_in[1];
    const float* vb = (const float*)d_in[2];
    const float* kw = (const float*)d_in[3];
    const float* kb = (const float*)d_in[4];
    const float* w1 = (const float*)d_in[5];
    const float* b1 = (const float*)d_in[6];
    const float* w2 = (const float*)d_in[7];
    const float* b2 = (const float*)d_in[8];
    const float* w3 = (const float*)d_in[9];
    const float* b3 = (const float*)d_in[10];
    float* out = (float*)d_out;

    k_init<<<NB + 1, 256>>>(vw, vb, w3);
    dim3 g1(NH / 2, NB);
    k_pass1<<<g1, 256>>>(x, kw, kb);
    dim3 g2(16, NB);
    k_smap<<<g2, 256>>>(w1, b1, w2, b2, b3);
    dim3 g3(NC, NB);
    k_xk<<<g3, 256>>>(x);
    dim3 g4(NC / 8, NB);
    k_cf<<<g4, 256>>>(vw, vb);
    dim3 g5(HW / 4 / 256, NC / 4, NB);
    k_out<<<g5, 256>>>(x, out);
}

// round 17
// speedup vs baseline: 1.6764x; 1.2793x over previous
#include <cuda_runtime.h>
#include <math.h>

#define NB 8
#define NC 256
#define NH 128
#define NW 128
#define HW (NH*NW)
#define POS 32
#define PAD 33

// ---------------- scratch (device globals) ----------------------------------
__device__ __align__(16) float g_ux[NB][HW];
__device__ __align__(16) float g_s[NB][HW];
__device__ float g_hmax[NB][NH];
__device__ float g_hsum[NB][NH];
__device__ float g_wmax[NB][NW];
__device__ float g_wsum[NB][NW];
__device__ float g_Z[NB];                        // softmax partition sum
__device__ float g_xk[NB][NC];                   // unnormalized weighted sum
__device__ float g_cf[NB][NC];
__device__ float g_u[NC];
__device__ float g_beta;

__device__ __forceinline__ void atomicMaxFloat(float* addr, float val) {
    if (val >= 0.f) atomicMax((int*)addr, __float_as_int(val));
    else            atomicMin((unsigned int*)addr, __float_as_uint(val));
}

// ---------------- kernel 0: init accumulators + u = v_w^T w3, beta ----------
__global__ __launch_bounds__(256) void k_init(const float* __restrict__ vw,
                                              const float* __restrict__ vb,
                                              const float* __restrict__ w3) {
    int t = threadIdx.x;
    if (blockIdx.x < NB) {
        int b = blockIdx.x;
        if (t < NH) {
            g_hmax[b][t] = -INFINITY; g_hsum[b][t] = 0.f;
            g_wmax[b][t] = -INFINITY; g_wsum[b][t] = 0.f;
        }
        g_xk[b][t] = 0.f;
        if (t == 0) g_Z[b] = 0.f;
    } else {
        float acc = 0.f;
#pragma unroll 8
        for (int o = 0; o < NC; o++) acc = fmaf(w3[o], vw[o*NC + t], acc);
        g_u[t] = acc;
        if (t == 0) {
            float ba = 0.f;
            for (int c = 0; c < NC; c++) ba = fmaf(w3[c], vb[c], ba);
            g_beta = ba;
        }
    }
}

// ---------------- kernel 1: FUSED single read of x --------------------------
// Tile: 256 channels x 32 positions (quarter of one h row), staged in smem.
// Phase A: kp = kw.x, ux = u.x, max/sum pools; e = exp(kp) (unnormalized).
// Phase B: xk[c] += sum_w x[c][w] * e[w]  (re-read from smem, not DRAM).
__global__ __launch_bounds__(256) void k_fused(const float* __restrict__ x,
                                               const float* __restrict__ kw_g,
                                               const float* __restrict__ kb_p) {
    __shared__ float sx[NC * PAD];          // 33.8 KB, pad-33: both phases conflict-free
    __shared__ float s_part[4 * 256];       // [stat][g][w] partials
    __shared__ float s_e[POS];
    __shared__ float s_kw[NC], s_u[NC];
    const int t  = threadIdx.x;
    const int b  = blockIdx.y;
    const int h  = blockIdx.x >> 2;
    const int q  = blockIdx.x & 3;
    const int w0 = q * POS;

    s_kw[t] = kw_g[t];
    s_u[t]  = g_u[t];

    // ---- load tile: 8 float4 per thread, coalesced ----
    const float* xb = x + (size_t)b * NC * HW + h * NW + w0;
#pragma unroll
    for (int i = 0; i < 8; i++) {
        int fid = t + i * 256;              // 0..2047
        int c   = fid >> 3;
        int v   = fid & 7;
        float4 val = *(const float4*)(xb + (size_t)c * HW + v * 4);
        float* dst = sx + c * PAD + v * 4;
        dst[0] = val.x; dst[1] = val.y; dst[2] = val.z; dst[3] = val.w;
    }
    __syncthreads();

    // ---- phase A: per-position partials over 32-channel groups ----
    {
        const int w = t & 31, g = t >> 5;
        float kp = 0.f, ux = 0.f, mx = -INFINITY, sm = 0.f;
#pragma unroll 8
        for (int j = 0; j < 32; j++) {
            int c = g * 32 + j;
            float v = sx[c * PAD + w];
            kp = fmaf(s_kw[c], v, kp);
            ux = fmaf(s_u[c],  v, ux);
            mx = fmaxf(mx, v);
            sm += v;
        }
        s_part[0 * 256 + g * 32 + w] = kp;
        s_part[1 * 256 + g * 32 + w] = ux;
        s_part[2 * 256 + g * 32 + w] = mx;
        s_part[3 * 256 + g * 32 + w] = sm;
    }
    __syncthreads();

    // ---- finalize per-position stats on warp 0 ----
    if (t < 32) {
        const int w = t;
        float kp = 0.f, ux = 0.f, mx = -INFINITY, sm = 0.f;
#pragma unroll
        for (int g = 0; g < 8; g++) {
            kp += s_part[0 * 256 + g * 32 + w];
            ux += s_part[1 * 256 + g * 32 + w];
            mx  = fmaxf(mx, s_part[2 * 256 + g * 32 + w]);
            sm += s_part[3 * 256 + g * 32 + w];
        }
        kp += kb_p[0];
        const float e = __expf(kp);          // unnormalized softmax weight
        s_e[w] = e;
        g_ux[b][h * NW + w0 + w] = ux;
        atomicMaxFloat(&g_wmax[b][w0 + w], mx);   // coalesced, 32 distinct addrs
        atomicAdd(&g_wsum[b][w0 + w], sm);
        float hm = mx, hs = sm, ze = e;
#pragma unroll
        for (int off = 16; off > 0; off >>= 1) {
            hm = fmaxf(hm, __shfl_down_sync(0xffffffffu, hm, off));
            hs += __shfl_down_sync(0xffffffffu, hs, off);
            ze += __shfl_down_sync(0xffffffffu, ze, off);
        }
        if (t == 0) {
            atomicMaxFloat(&g_hmax[b][h], hm);
            atomicAdd(&g_hsum[b][h], hs);
            atomicAdd(&g_Z[b], ze);
        }
    }
    __syncthreads();

    // ---- phase B: xk partial from smem (thread t = channel) ----
    {
        float acc = 0.f;
        const float* row = sx + t * PAD;     // lanes stride 33 -> conflict-free
#pragma unroll 8
        for (int w = 0; w < POS; w++) acc = fmaf(row[w], s_e[w], acc);
        atomicAdd(&g_xk[b][t], acc);         // 256 consecutive addrs: coalesced REDG
    }
}

// ---------------- kernel 2: attentions (smem) + s map, wide grid ------------
__global__ __launch_bounds__(256) void k_smap(const float* __restrict__ w1,
                                              const float* __restrict__ b1,
                                              const float* __restrict__ w2,
                                              const float* __restrict__ b2,
                                              const float* __restrict__ b3) {
    __shared__ float s_att[256];         // [0:128) hatt, [128:256) watt
    const int b = blockIdx.y, t = threadIdx.x;

    if (t < NH) {
        float havg = g_hsum[b][t] * (1.f / (NC * NW));
        float v = fmaf(w1[0], g_hmax[b][t], fmaf(w1[1], havg, b1[0]));
        s_att[t] = 1.f / (1.f + __expf(-v));
    } else {
        int w = t - 128;
        float wavg = g_wsum[b][w] * (1.f / (NC * NH));
        float v = fmaf(w2[0], g_wmax[b][w], fmaf(w2[1], wavg, b2[0]));
        s_att[t] = 1.f / (1.f + __expf(-v));
    }
    __syncthreads();

    const float beta = g_beta, bb3 = b3[0];
    const int base = blockIdx.x * 1024;
#pragma unroll
    for (int i = 0; i < 4; i++) {
        int n  = base + t + i * 256;
        int hh = n >> 7, ww = n & 127;
        float att = s_att[hh] + s_att[128 + ww];
        float sp  = fmaf(att, g_ux[b][n] + beta, bb3);
        g_s[b][n] = 1.f / (1.f + __expf(-sp));
    }
}

// ---------------- kernel 3: cf = (v_w @ xk)/Z + v_b  (coalesced) ------------
__global__ __launch_bounds__(256) void k_cf(const float* __restrict__ vw,
                                            const float* __restrict__ vb) {
    const int b    = blockIdx.y;
    const int warp = threadIdx.x >> 5;
    const int lane = threadIdx.x & 31;
    const int o    = blockIdx.x * 8 + warp;
    __shared__ float s_xk[NC];
    s_xk[threadIdx.x] = g_xk[b][threadIdx.x];
    __syncthreads();

    const float4* vw4 = (const float4*)(vw + (size_t)o * NC);
    float acc = 0.f;
#pragma unroll
    for (int half = 0; half < 2; half++) {
        float4 v = vw4[half * 32 + lane];
        int cb = (half * 32 + lane) * 4;
        acc = fmaf(v.x, s_xk[cb + 0], acc);
        acc = fmaf(v.y, s_xk[cb + 1], acc);
        acc = fmaf(v.z, s_xk[cb + 2], acc);
        acc = fmaf(v.w, s_xk[cb + 3], acc);
    }
#pragma unroll
    for (int off = 16; off > 0; off >>= 1)
        acc += __shfl_down_sync(0xffffffffu, acc, off);
    if (lane == 0)
        g_cf[b][o] = fmaf(acc, 1.f / g_Z[b], vb[o]);
}

// ---------------- kernel 4: out = s*cf + x, 4 channels per block ------------
__global__ __launch_bounds__(256) void k_out(const float* __restrict__ x,
                                             float* __restrict__ out) {
    const int b  = blockIdx.z;
    const int cg = blockIdx.y;
    const int n4 = blockIdx.x * 256 + threadIdx.x;

    const float4 sv = ((const float4*)g_s[b])[n4];
    float cf[4];
#pragma unroll
    for (int i = 0; i < 4; i++) cf[i] = g_cf[b][cg * 4 + i];

    const size_t base = ((size_t)(b * NC + cg * 4)) * (HW / 4) + n4;
    const float4* x4 = (const float4*)x;
    float4*       o4 = (float4*)out;
#pragma unroll
    for (int i = 0; i < 4; i++) {
        float4 xv = x4[base + (size_t)i * (HW / 4)];
        float4 o;
        o.x = fmaf(sv.x, cf[i], xv.x);
        o.y = fmaf(sv.y, cf[i], xv.y);
        o.z = fmaf(sv.z, cf[i], xv.z);
        o.w = fmaf(sv.w, cf[i], xv.w);
        o4[base + (size_t)i * (HW / 4)] = o;
    }
}

// ---------------- launch ----------------------------------------------------
extern "C" void kernel_launch(void* const* d_in, const int* in_sizes, int n_in,
                              void* d_out, int out_size) {
    const float* x  = (const float*)d_in[0];
    const float* vw = (const float*)d_in[1];
    const float* vb = (const float*)d_in[2];
    const float* kw = (const float*)d_in[3];
    const float* kb = (const float*)d_in[4];
    const float* w1 = (const float*)d_in[5];
    const float* b1 = (const float*)d_in[6];
    const float* w2 = (const float*)d_in[7];
    const float* b2 = (const float*)d_in[8];
    const float* w3 = (const float*)d_in[9];
    const float* b3 = (const float*)d_in[10];
    float* out = (float*)d_out;

    k_init<<<NB + 1, 256>>>(vw, vb, w3);
    dim3 g1(NH * 4, NB);                 // 4 quarter-row tiles per h
    k_fused<<<g1, 256>>>(x, kw, kb);
    dim3 g2(16, NB);
    k_smap<<<g2, 256>>>(w1, b1, w2, b2, b3);
    dim3 g4(NC / 8, NB);
    k_cf<<<g4, 256>>>(vw, vb);
    dim3 g5(HW / 4 / 256, NC / 4, NB);
    k_out<<<g5, 256>>>(x, out);
}